// round 5
// baseline (speedup 1.0000x reference)
#include <cuda_runtime.h>
#include <cuda_bf16.h>
#include <cstdint>

// ExpandHarmonics. Output (float32): [hkl 3M | dHKL M | wav M | meta DM*M].
// R5: register shuffle-shift meta copy (all LDG/STG 16B-aligned, no smem),
//     scalar outputs fused into the pack pass.

#define MAXN   (1 << 20)
#define BLK    256
#define MAXB   ((MAXN + BLK - 1) / BLK)
#define MAXM   (1 << 23)

__device__ int           g_rowoff[MAXN];
__device__ unsigned char g_cnt[MAXN];
__device__ int           g_blocksum[MAXB + 1];
__device__ int           g_pack[MAXM];       // (src_idx << 8) | harmonic_n
__device__ unsigned int  g_hkl0[MAXN];       // h0 | k0<<8 | l0<<16
__device__ float         g_d0[MAXN];         // dHKL * g
__device__ float         g_w0[MAXN];         // wavelength * g

__device__ __forceinline__ int gcd2(int a, int b) {
    while (b) { int t = a % b; a = b; b = t; }
    return a;
}

// ---- Pass 1: per-row count + precompute + in-block scan ----
__global__ __launch_bounds__(BLK)
void k_count(const int* __restrict__ hkl, const float* __restrict__ dHKL,
             const float* __restrict__ wav, const float* __restrict__ dmin, int N) {
    __shared__ int s[BLK];
    int i = blockIdx.x * BLK + threadIdx.x;
    int cnt = 0;
    if (i < N) {
        int h = hkl[3 * i], k = hkl[3 * i + 1], l = hkl[3 * i + 2];
        int g = gcd2(gcd2(h, k), l);
        float fg = (float)g;
        float d0 = dHKL[i] * fg;
        cnt = (int)floorf(d0 / dmin[0]);
        g_hkl0[i] = (unsigned)(h / g) | ((unsigned)(k / g) << 8) | ((unsigned)(l / g) << 16);
        g_d0[i] = d0;
        g_w0[i] = wav[i] * fg;
    }
    s[threadIdx.x] = cnt;
    __syncthreads();
    #pragma unroll
    for (int off = 1; off < BLK; off <<= 1) {
        int t = (threadIdx.x >= off) ? s[threadIdx.x - off] : 0;
        __syncthreads();
        s[threadIdx.x] += t;
        __syncthreads();
    }
    if (i < N) {
        g_rowoff[i] = s[threadIdx.x] - cnt;
        g_cnt[i]    = (unsigned char)cnt;
    }
    if (threadIdx.x == 0) g_blocksum[blockIdx.x] = s[BLK - 1];
}

// ---- Pass 2: single-block exclusive scan of block sums ----
__global__ __launch_bounds__(1024)
void k_scan_blocks(int B) {
    __shared__ int s[1024];
    int tid = threadIdx.x;
    int ipt = (B + 1023) / 1024;
    int local[8];
    int start = tid * ipt;
    int sum = 0;
    for (int j = 0; j < ipt; j++) {
        int idx = start + j;
        int v = (idx < B) ? g_blocksum[idx] : 0;
        local[j] = sum;
        sum += v;
    }
    s[tid] = sum;
    __syncthreads();
    #pragma unroll
    for (int off = 1; off < 1024; off <<= 1) {
        int t = (tid >= off) ? s[tid - off] : 0;
        __syncthreads();
        s[tid] += t;
        __syncthreads();
    }
    int base = s[tid] - sum;
    for (int j = 0; j < ipt; j++) {
        int idx = start + j;
        if (idx < B) g_blocksum[idx] = base + local[j];
    }
    if (tid == 1023) g_blocksum[B] = s[1023];
}

// ---- Pass 3: pack + all scalar outputs, per input row ----
__global__ __launch_bounds__(BLK)
void k_pack_scalar(float* __restrict__ out, int N, int M) {
    int i = blockIdx.x * BLK + threadIdx.x;
    if (i >= N) return;
    int off = g_rowoff[i] + g_blocksum[blockIdx.x];
    int cnt = g_cnt[i];
    unsigned hp = g_hkl0[i];
    float d0 = g_d0[i], w0 = g_w0[i];
    int h0 = (int)(hp & 255u), k0 = (int)((hp >> 8) & 255u), l0 = (int)(hp >> 16);
    int tag = i << 8;
    for (int n = 1; n <= cnt; n++) {
        int m = off + n - 1;
        g_pack[m] = tag | n;
        float fn = (float)n;
        out[3 * m + 0] = (float)(h0 * n);
        out[3 * m + 1] = (float)(k0 * n);
        out[3 * m + 2] = (float)(l0 * n);
        out[3 * M + m] = d0 / fn;
        out[4 * M + m] = w0 / fn;
    }
}

// ---- Pass 4: meta copy via register shuffle-shift (DM power of two) ----
// Region coords: p in [0, T), T = M*DM. Output float p lives at out[5M + p].
// lead = (4 - (5M)%4)%4: out[5M+lead] is the first 16B-aligned slot.
// Warp chunk = 128 floats. Lane j holds source group v = elements [128w+4j, +4)
// (aligned float4 gather). Output float4 f covers [lead+4f, +4) -> composed from
// v[j], v[j+1] with uniform element shift 'lead'.
__global__ __launch_bounds__(256)
void k_meta3(const float* __restrict__ meta, float* __restrict__ out, int M, int DMs) {
    const unsigned DMm = (1u << DMs) - 1u;
    const size_t T = (size_t)M << DMs;
    const size_t gbase = (size_t)5 * M;
    const int lead = (int)((4 - (gbase & 3)) & 3);
    const size_t NV = (T - (size_t)lead) >> 2;

    int w    = (blockIdx.x * 256 + threadIdx.x) >> 5;
    int lane = threadIdx.x & 31;
    size_t base = (size_t)w << 7;                 // 128 floats per warp
    size_t p = base + 4 * (size_t)lane;

    float4 v = make_float4(0.f, 0.f, 0.f, 0.f);
    if (p < T) {                                  // T%4==0 -> group fully inside
        int r = (int)(p >> DMs);
        int e = (int)(p & DMm);
        int idx = g_pack[r] >> 8;
        v = *(const float4*)(meta + ((size_t)idx << DMs) + e);
    }

    float4 o4;
    if (lead == 0) {
        o4 = v;
    } else {
        float4 vnl = make_float4(0.f, 0.f, 0.f, 0.f);
        if (lane == 31) {
            size_t p2 = base + 128;
            if (p2 < T) {
                int r = (int)(p2 >> DMs);
                int e = (int)(p2 & DMm);
                int idx = g_pack[r] >> 8;
                vnl = *(const float4*)(meta + ((size_t)idx << DMs) + e);
            }
        }
        float4 sn;
        sn.x = __shfl_down_sync(0xffffffffu, v.x, 1);
        sn.y = __shfl_down_sync(0xffffffffu, v.y, 1);
        sn.z = __shfl_down_sync(0xffffffffu, v.z, 1);
        sn.w = __shfl_down_sync(0xffffffffu, v.w, 1);
        float4 vn = (lane == 31) ? vnl : sn;
        if (lead == 1)      o4 = make_float4(v.y, v.z, v.w, vn.x);
        else if (lead == 2) o4 = make_float4(v.z, v.w, vn.x, vn.y);
        else                o4 = make_float4(v.w, vn.x, vn.y, vn.z);
    }

    size_t f = (base >> 2) + (size_t)lane;
    if (f < NV)
        *(float4*)(out + gbase + (size_t)lead + 4 * f) = o4;

    // head + tail scalars (block 0, warp 0), direct loads
    if (blockIdx.x == 0 && threadIdx.x < 32) {
        if (lane < lead) {
            int idx = g_pack[0] >> 8;
            out[gbase + lane] = meta[((size_t)idx << DMs) + lane];
        }
        int tail = (int)(T - (size_t)lead - 4 * NV);   // 0..3
        if (lane >= 4 && lane < 4 + tail) {
            size_t pp = (size_t)lead + 4 * NV + (size_t)(lane - 4);
            int r = (int)(pp >> DMs);
            int e = (int)(pp & DMm);
            int idx = g_pack[r] >> 8;
            out[gbase + pp] = meta[((size_t)idx << DMs) + e];
        }
    }
}

// ---- Fallback meta copy (DM not a power of two) ----
__global__ __launch_bounds__(256)
void k_meta_fb(const float* __restrict__ meta, float* __restrict__ out, int M, int DM) {
    int gw   = (blockIdx.x * 256 + threadIdx.x) >> 5;
    int lane = threadIdx.x & 31;
    int r = lane >> 3;
    int c = lane & 7;
    int m = gw * 4 + r;
    if (m >= M) return;
    int idx = g_pack[m] >> 8;
    const float* src = meta + (size_t)idx * DM;
    float*       dst = out + (size_t)5 * M + (size_t)m * DM;
    for (int e = c; e < DM; e += 8)
        dst[e] = src[e];
}

extern "C" void kernel_launch(void* const* d_in, const int* in_sizes, int n_in,
                              void* d_out, int out_size) {
    const int*   hkl  = (const int*)  d_in[0];
    const float* dHKL = (const float*)d_in[1];
    const float* wav  = (const float*)d_in[2];
    const float* meta = (const float*)d_in[3];
    const float* dmin = (const float*)d_in[4];

    int N  = in_sizes[1];
    int DM = in_sizes[3] / N;
    int M  = out_size / (5 + DM);

    int B = (N + BLK - 1) / BLK;

    k_count<<<B, BLK>>>(hkl, dHKL, wav, dmin, N);
    k_scan_blocks<<<1, 1024>>>(B);
    k_pack_scalar<<<B, BLK>>>((float*)d_out, N, M);

    bool pow2 = (DM >= 4) && ((DM & (DM - 1)) == 0);
    if (pow2) {
        int DMs = 0; while ((1 << DMs) < DM) DMs++;
        size_t T = (size_t)M * DM;
        size_t warps = (T + 127) / 128;
        int grid = (int)((warps + 7) / 8);
        k_meta3<<<grid, 256>>>(meta, (float*)d_out, M, DMs);
    } else {
        int rowsPerBlock = 8 * 4;
        k_meta_fb<<<(M + rowsPerBlock - 1) / rowsPerBlock, 256>>>(meta, (float*)d_out, M, DM);
    }
}

// round 6
// speedup vs baseline: 1.3575x; 1.3575x over previous
#include <cuda_runtime.h>
#include <cuda_bf16.h>
#include <cstdint>

// ExpandHarmonics. Output (float32): [hkl 3M | dHKL M | wav M | meta DM*M].
// R6: 4x-batched shuffle-shift meta copy (templated LEAD), 32-bit index math,
//     scalar outputs as extra blocks of the same kernel, cheap pack pass.

#define MAXN   (1 << 20)
#define BLK    256
#define MAXB   ((MAXN + BLK - 1) / BLK)
#define MAXM   (1 << 23)

__device__ int           g_rowoff[MAXN];
__device__ unsigned char g_cnt[MAXN];
__device__ int           g_blocksum[MAXB + 1];
__device__ int           g_pack[MAXM];       // (src_idx << 8) | harmonic_n
__device__ unsigned int  g_hkl0[MAXN];       // h0 | k0<<8 | l0<<16
__device__ float         g_d0[MAXN];         // dHKL * g
__device__ float         g_w0[MAXN];         // wavelength * g

__device__ __forceinline__ int gcd2(int a, int b) {
    while (b) { int t = a % b; a = b; b = t; }
    return a;
}

// ---- Pass 1: per-row count + precompute + in-block scan ----
__global__ __launch_bounds__(BLK)
void k_count(const int* __restrict__ hkl, const float* __restrict__ dHKL,
             const float* __restrict__ wav, const float* __restrict__ dmin, int N) {
    __shared__ int s[BLK];
    int i = blockIdx.x * BLK + threadIdx.x;
    int cnt = 0;
    if (i < N) {
        int h = hkl[3 * i], k = hkl[3 * i + 1], l = hkl[3 * i + 2];
        int g = gcd2(gcd2(h, k), l);
        float fg = (float)g;
        float d0 = dHKL[i] * fg;
        cnt = (int)floorf(d0 / dmin[0]);
        g_hkl0[i] = (unsigned)(h / g) | ((unsigned)(k / g) << 8) | ((unsigned)(l / g) << 16);
        g_d0[i] = d0;
        g_w0[i] = wav[i] * fg;
    }
    s[threadIdx.x] = cnt;
    __syncthreads();
    #pragma unroll
    for (int off = 1; off < BLK; off <<= 1) {
        int t = (threadIdx.x >= off) ? s[threadIdx.x - off] : 0;
        __syncthreads();
        s[threadIdx.x] += t;
        __syncthreads();
    }
    if (i < N) {
        g_rowoff[i] = s[threadIdx.x] - cnt;
        g_cnt[i]    = (unsigned char)cnt;
    }
    if (threadIdx.x == 0) g_blocksum[blockIdx.x] = s[BLK - 1];
}

// ---- Pass 2: single-block exclusive scan of block sums ----
__global__ __launch_bounds__(1024)
void k_scan_blocks(int B) {
    __shared__ int s[1024];
    int tid = threadIdx.x;
    int ipt = (B + 1023) / 1024;
    int local[8];
    int start = tid * ipt;
    int sum = 0;
    for (int j = 0; j < ipt; j++) {
        int idx = start + j;
        int v = (idx < B) ? g_blocksum[idx] : 0;
        local[j] = sum;
        sum += v;
    }
    s[tid] = sum;
    __syncthreads();
    #pragma unroll
    for (int off = 1; off < 1024; off <<= 1) {
        int t = (tid >= off) ? s[tid - off] : 0;
        __syncthreads();
        s[tid] += t;
        __syncthreads();
    }
    int base = s[tid] - sum;
    for (int j = 0; j < ipt; j++) {
        int idx = start + j;
        if (idx < B) g_blocksum[idx] = base + local[j];
    }
    if (tid == 1023) g_blocksum[B] = s[1023];
}

// ---- Pass 3: per-output-row (idx, n) pack ----
__global__ __launch_bounds__(BLK)
void k_pack(int N) {
    int i = blockIdx.x * BLK + threadIdx.x;
    if (i >= N) return;
    int off = g_rowoff[i] + g_blocksum[blockIdx.x];
    int cnt = g_cnt[i];
    int tag = i << 8;
    for (int n = 1; n <= cnt; n++)
        g_pack[off + n - 1] = tag | n;
}

// ---- Pass 4 (fused): meta copy (blocks [0, metaBlocks)) + scalar outputs ----
// Meta region coords: src float p (= out[5M+p]), p in [0, T), T = M*DM.
// LEAD = (4-(5M)%4)%4 : out[5M+LEAD] is the first 16B-aligned slot.
// Warp chunk = 512 floats; lane j owns src floats [512w+16j, +16) as 4 aligned
// float4 loads, composes 4 LEAD-shifted float4s (needs next lane's first group
// via shuffle; lane 31 loads the next chunk's first group), 4 aligned stores.
template<int LEAD>
__global__ __launch_bounds__(256)
void k_fused(const float* __restrict__ meta, float* __restrict__ out,
             int M, int DMs, unsigned T, unsigned NV, int metaBlocks) {
    // ---------- scalar-output blocks ----------
    if ((int)blockIdx.x >= metaBlocks) {
        int m = (blockIdx.x - metaBlocks) * 256 + threadIdx.x;
        if (m < M) {
            int pack = g_pack[m];
            int idx = pack >> 8;
            int n   = pack & 255;
            unsigned hp = g_hkl0[idx];
            float fn = (float)n;
            out[3 * m + 0] = (float)((int)(hp & 255u) * n);
            out[3 * m + 1] = (float)((int)((hp >> 8) & 255u) * n);
            out[3 * m + 2] = (float)((int)(hp >> 16) * n);
            out[3 * M + m] = g_d0[idx] / fn;
            out[4 * M + m] = g_w0[idx] / fn;
        }
        return;
    }

    // ---------- meta-copy blocks ----------
    const unsigned DMm = (1u << DMs) - 1u;
    const size_t gbase = (size_t)5 * M;

    unsigned w    = blockIdx.x * 8u + (threadIdx.x >> 5);
    int      lane = threadIdx.x & 31;
    unsigned base = w * 512u + (unsigned)lane * 16u;   // lane's first src float

    float a[20];
    #pragma unroll
    for (int u = 0; u < 4; u++) {
        unsigned p = base + 4u * u;
        float4 v = make_float4(0.f, 0.f, 0.f, 0.f);
        if (p < T) {
            unsigned idx = ((unsigned)__ldg(&g_pack[p >> DMs])) >> 8;
            v = *(const float4*)(meta + (size_t)((idx << DMs) + (p & DMm)));
        }
        a[4 * u + 0] = v.x; a[4 * u + 1] = v.y; a[4 * u + 2] = v.z; a[4 * u + 3] = v.w;
    }

    if (LEAD != 0) {
        // a[16..19] = next lane's first group (lane 31: next warp chunk's first group)
        float4 nx = make_float4(0.f, 0.f, 0.f, 0.f);
        if (lane == 31) {
            unsigned p2 = w * 512u + 512u;
            if (p2 < T) {
                unsigned idx = ((unsigned)__ldg(&g_pack[p2 >> DMs])) >> 8;
                nx = *(const float4*)(meta + (size_t)((idx << DMs) + (p2 & DMm)));
            }
        }
        float s0 = __shfl_down_sync(0xffffffffu, a[0], 1);
        float s1 = __shfl_down_sync(0xffffffffu, a[1], 1);
        float s2 = __shfl_down_sync(0xffffffffu, a[2], 1);
        float s3 = __shfl_down_sync(0xffffffffu, a[3], 1);
        a[16] = (lane == 31) ? nx.x : s0;
        a[17] = (lane == 31) ? nx.y : s1;
        a[18] = (lane == 31) ? nx.z : s2;
        a[19] = (lane == 31) ? nx.w : s3;
    }

    unsigned f0 = w * 128u + (unsigned)lane * 4u;      // first output vector index
    float* dstf = out + gbase + (size_t)LEAD;
    #pragma unroll
    for (int k2 = 0; k2 < 4; k2++) {
        unsigned f = f0 + (unsigned)k2;
        if (f < NV) {
            float4 o = make_float4(a[LEAD + 4 * k2 + 0], a[LEAD + 4 * k2 + 1],
                                   a[LEAD + 4 * k2 + 2], a[LEAD + 4 * k2 + 3]);
            *(float4*)(dstf + 4 * (size_t)f) = o;
        }
    }

    // head + tail scalars
    if (blockIdx.x == 0 && threadIdx.x < 32) {
        if (lane < LEAD) {
            unsigned idx = ((unsigned)g_pack[0]) >> 8;
            out[gbase + lane] = meta[(size_t)((idx << DMs) + lane)];
        }
        unsigned done = (unsigned)LEAD + 4u * NV;
        unsigned tail = T - done;                       // 0..3
        if (lane >= 4 && lane < 4 + (int)tail) {
            unsigned p = done + (unsigned)(lane - 4);
            unsigned idx = ((unsigned)g_pack[p >> DMs]) >> 8;
            out[gbase + p] = meta[(size_t)((idx << DMs) + (p & DMm))];
        }
    }
}

// ---- Fallbacks (DM not power of two) ----
__global__ __launch_bounds__(256)
void k_scalar_fb(float* __restrict__ out, int M) {
    int m = blockIdx.x * 256 + threadIdx.x;
    if (m >= M) return;
    int pack = g_pack[m];
    int idx = pack >> 8;
    int n   = pack & 255;
    unsigned hp = g_hkl0[idx];
    float fn = (float)n;
    out[3 * m + 0] = (float)((int)(hp & 255u) * n);
    out[3 * m + 1] = (float)((int)((hp >> 8) & 255u) * n);
    out[3 * m + 2] = (float)((int)(hp >> 16) * n);
    out[3 * M + m] = g_d0[idx] / fn;
    out[4 * M + m] = g_w0[idx] / fn;
}

__global__ __launch_bounds__(256)
void k_meta_fb(const float* __restrict__ meta, float* __restrict__ out, int M, int DM) {
    int gw   = (blockIdx.x * 256 + threadIdx.x) >> 5;
    int lane = threadIdx.x & 31;
    int r = lane >> 3;
    int c = lane & 7;
    int m = gw * 4 + r;
    if (m >= M) return;
    int idx = g_pack[m] >> 8;
    const float* src = meta + (size_t)idx * DM;
    float*       dst = out + (size_t)5 * M + (size_t)m * DM;
    for (int e = c; e < DM; e += 8)
        dst[e] = src[e];
}

extern "C" void kernel_launch(void* const* d_in, const int* in_sizes, int n_in,
                              void* d_out, int out_size) {
    const int*   hkl  = (const int*)  d_in[0];
    const float* dHKL = (const float*)d_in[1];
    const float* wav  = (const float*)d_in[2];
    const float* meta = (const float*)d_in[3];
    const float* dmin = (const float*)d_in[4];

    int N  = in_sizes[1];
    int DM = in_sizes[3] / N;
    int M  = out_size / (5 + DM);

    int B = (N + BLK - 1) / BLK;

    k_count<<<B, BLK>>>(hkl, dHKL, wav, dmin, N);
    k_scan_blocks<<<1, 1024>>>(B);
    k_pack<<<B, BLK>>>(N);

    bool pow2 = (DM >= 4) && ((DM & (DM - 1)) == 0);
    if (pow2) {
        int DMs = 0; while ((1 << DMs) < DM) DMs++;
        unsigned T = (unsigned)((size_t)M << DMs);
        int lead = (int)((4u - ((5u * (unsigned)M) & 3u)) & 3u);
        unsigned NV = (T - (unsigned)lead) >> 2;
        unsigned metaWarps = (NV + 127u) / 128u;
        int metaBlocks = (int)((metaWarps + 7u) / 8u);
        int scalarBlocks = (M + 255) / 256;
        int grid = metaBlocks + scalarBlocks;
        switch (lead) {
            case 0: k_fused<0><<<grid, 256>>>(meta, (float*)d_out, M, DMs, T, NV, metaBlocks); break;
            case 1: k_fused<1><<<grid, 256>>>(meta, (float*)d_out, M, DMs, T, NV, metaBlocks); break;
            case 2: k_fused<2><<<grid, 256>>>(meta, (float*)d_out, M, DMs, T, NV, metaBlocks); break;
            default: k_fused<3><<<grid, 256>>>(meta, (float*)d_out, M, DMs, T, NV, metaBlocks); break;
        }
    } else {
        k_scalar_fb<<<(M + 255) / 256, 256>>>((float*)d_out, M);
        int rowsPerBlock = 8 * 4;
        k_meta_fb<<<(M + rowsPerBlock - 1) / rowsPerBlock, 256>>>(meta, (float*)d_out, M, DM);
    }
}